// round 3
// baseline (speedup 1.0000x reference)
#include <cuda_runtime.h>
#include <cstdint>
#include <cstddef>

#define NN 4096
#define FD 256
#define HD 256
#define KG 3
#define G4 1024
#define TST 5

// ---------------- scratch (device globals: no runtime allocation) ----------------
static __device__ float g_rx[NN*FD];
static __device__ float g_rgw[KG*FD*HD];
static __device__ float g_rwih[KG*G4*HD];
static __device__ float g_rwhh[KG*G4*HD];
static __device__ float g_rfcw[KG*FD*HD];
static __device__ float g_dinv[KG*NN];
static __device__ float g_xw[(size_t)KG*NN*HD];
static __device__ float g_s[(size_t)KG*NN*HD];
static __device__ float g_gnn[(size_t)KG*NN*HD];
static __device__ float g_xtp[(size_t)KG*NN*G4];
static __device__ float g_gates[(size_t)KG*NN*G4];
static __device__ float g_h[(size_t)KG*NN*HD];
static __device__ float g_c[(size_t)KG*NN*HD];
static __device__ float g_delta[(size_t)KG*NN*FD];

// ---------------- helpers ----------------
__device__ __forceinline__ float rna(float x){
    uint32_t u; asm("cvt.rna.tf32.f32 %0, %1;" : "=r"(u) : "f"(x));
    return __uint_as_float(u);
}

__device__ __forceinline__ void mma_tf32(float* c, const uint32_t* a, const uint32_t* b){
    asm volatile(
        "mma.sync.aligned.m16n8k8.row.col.f32.tf32.tf32.f32 "
        "{%0,%1,%2,%3}, {%4,%5,%6,%7}, {%8,%9}, {%0,%1,%2,%3};"
        : "+f"(c[0]), "+f"(c[1]), "+f"(c[2]), "+f"(c[3])
        : "r"(a[0]), "r"(a[1]), "r"(a[2]), "r"(a[3]), "r"(b[0]), "r"(b[1]));
}

__device__ __forceinline__ float sigf(float x){
    x = fminf(fmaxf(x, -30.f), 30.f);
    return __fdividef(1.f, 1.f + __expf(-x));
}
__device__ __forceinline__ float tanhf_(float x){
    x = fminf(fmaxf(x, -15.f), 15.f);
    float e = __expf(2.f*x);
    return __fdividef(e - 1.f, e + 1.f);
}

// ---------------- prep: round fp32 operands to tf32 ----------------
__global__ void __launch_bounds__(256) prep_round(
    const float* __restrict__ x, const float* __restrict__ gw,
    const float* __restrict__ wih, const float* __restrict__ whh,
    const float* __restrict__ fcw)
{
    int i = blockIdx.x*blockDim.x + threadIdx.x;
    int stride = gridDim.x*blockDim.x;
    for (int t = i; t < NN*FD; t += stride)       g_rx[t]   = rna(x[t]);
    for (int t = i; t < KG*FD*HD; t += stride)    g_rgw[t]  = rna(gw[t]);
    for (int t = i; t < KG*G4*HD; t += stride)    g_rwih[t] = rna(wih[t]);
    for (int t = i; t < KG*G4*HD; t += stride)    g_rwhh[t] = rna(whh[t]);
    for (int t = i; t < KG*FD*HD; t += stride)    g_rfcw[t] = rna(fcw[t]);
}

// ---------------- adj pass: passthrough conversion + degree -> dinv ----------------
// one block per row i; reads adj row (12288 ints), writes float passthrough,
// reduces per-k degree, writes dinv = rsqrt(deg+1).
__global__ void __launch_bounds__(256) adj_pass(const int* __restrict__ adj,
                                                float* __restrict__ out_adj)
{
    int row = blockIdx.x;
    const int4* src = reinterpret_cast<const int4*>(adj + (size_t)row*NN*KG);
    float4* dst = reinterpret_cast<float4*>(out_adj + (size_t)row*NN*KG);
    int s0 = 0, s1 = 0, s2 = 0;
    #pragma unroll
    for (int it = 0; it < 12; it++){
        int l4 = threadIdx.x + it*256;
        int4 v = src[l4];
        int o = l4*4;
        int km = o % 3;
        int a0 = (v.x != 0), a1 = (v.y != 0), a2 = (v.z != 0), a3 = (v.w != 0);
        if (km == 0){ s0 += a0 + a3; s1 += a1; s2 += a2; }
        else if (km == 1){ s1 += a0 + a3; s2 += a1; s0 += a2; }
        else { s2 += a0 + a3; s0 += a1; s1 += a2; }
        dst[l4] = make_float4((float)v.x, (float)v.y, (float)v.z, (float)v.w);
    }
    __shared__ int sm[3];
    if (threadIdx.x < 3) sm[threadIdx.x] = 0;
    __syncthreads();
    s0 = __reduce_add_sync(0xffffffffu, s0);
    s1 = __reduce_add_sync(0xffffffffu, s1);
    s2 = __reduce_add_sync(0xffffffffu, s2);
    if ((threadIdx.x & 31) == 0){
        atomicAdd(&sm[0], s0); atomicAdd(&sm[1], s1); atomicAdd(&sm[2], s2);
    }
    __syncthreads();
    if (threadIdx.x < 3){
        float deg = (float)(sm[threadIdx.x] + 1);  // + self-loop
        g_dinv[threadIdx.x*NN + row] = rsqrtf(deg);
    }
}

// ---------------- epilogue functors ----------------
struct EpiXW {
    __device__ void operator()(int k, int r, int c, float v) const {
        size_t idx = ((size_t)k*NN + r)*HD + c;
        g_xw[idx] = v;                              // exact x@w (no bias) for self-loop term
        g_s[idx]  = rna(g_dinv[k*NN + r] * v);      // row-scaled, tf32-rounded
    }
};
struct EpiXTP {
    const float* b_ih; const float* b_hh;
    __device__ void operator()(int k, int r, int c, float v) const {
        g_xtp[((size_t)k*NN + r)*G4 + c] = v + b_ih[k*G4 + c] + b_hh[k*G4 + c];
    }
};
struct EpiGates {
    __device__ void operator()(int k, int r, int c, float v) const {
        size_t idx = ((size_t)k*NN + r)*G4 + c;
        g_gates[idx] = v + g_xtp[idx];
    }
};
struct EpiFC {
    const float* fc_b;
    __device__ void operator()(int k, int r, int c, float v) const {
        g_delta[((size_t)k*NN + r)*FD + c] = tanhf_(v + fc_b[k*FD + c]);
    }
};

// ---------------- generic tf32 GEMM, M=4096, Kdim=256, batched over k ----------------
// A row-major [4096,256] (selected scratch buffer), B either row-major [256,NC]
// or (BTRANS) row-major [NC,256] used as B^T. BM=128, BN=64, BK=32, 256 thr.
template<int NC, bool BTRANS, class Epi>
__global__ void __launch_bounds__(256) gemm_k256(int a_sel, int b_sel, Epi epi)
{
    constexpr int BM = 128, BN = 64, BK = 32, KD = 256;
    __shared__ float As[BK][BM+4];
    __shared__ float Bs[BK][BN+4];

    int kb = blockIdx.z;
    int m0 = blockIdx.y*BM;
    int n0 = blockIdx.x*BN;

    const float* A;
    if (a_sel == 0)      A = g_rx;
    else if (a_sel == 1) A = g_gnn + (size_t)kb*NN*HD;
    else                 A = g_h   + (size_t)kb*NN*HD;

    const float* B; size_t sb;
    if (b_sel == 0){ B = g_rgw;  sb = (size_t)FD*HD; }
    else if (b_sel == 1){ B = g_rwih; sb = (size_t)G4*HD; }
    else if (b_sel == 2){ B = g_rwhh; sb = (size_t)G4*HD; }
    else { B = g_rfcw; sb = (size_t)FD*HD; }
    B += (size_t)kb*sb;

    int tid = threadIdx.x, lane = tid & 31, wid = tid >> 5;
    int wm = wid & 3, wn = wid >> 2;       // 4 x 2 warps, each 32m x 32n
    int g = lane >> 2, t4 = lane & 3;

    float acc[2][4][4];
    #pragma unroll
    for (int a = 0; a < 2; a++)
        #pragma unroll
        for (int b = 0; b < 4; b++)
            #pragma unroll
            for (int e = 0; e < 4; e++) acc[a][b][e] = 0.f;

    for (int kt = 0; kt < KD/BK; kt++){
        // As: A[m0+row][kt*32 + c]
        #pragma unroll
        for (int it = 0; it < 4; it++){
            int idx = tid + it*256;
            int row = idx >> 3, c4 = (idx & 7)*4;
            float4 v = *reinterpret_cast<const float4*>(&A[(size_t)(m0+row)*KD + kt*BK + c4]);
            As[c4+0][row] = v.x; As[c4+1][row] = v.y; As[c4+2][row] = v.z; As[c4+3][row] = v.w;
        }
        if (!BTRANS){
            #pragma unroll
            for (int it = 0; it < 2; it++){
                int idx = tid + it*256;
                int r = idx >> 4, c4 = (idx & 15)*4;
                float4 v = *reinterpret_cast<const float4*>(&B[(size_t)(kt*BK + r)*NC + n0 + c4]);
                *reinterpret_cast<float4*>(&Bs[r][c4]) = v;
            }
        } else {
            #pragma unroll
            for (int it = 0; it < 2; it++){
                int idx = tid + it*256;
                int n = idx >> 3, k4 = (idx & 7)*4;
                float4 v = *reinterpret_cast<const float4*>(&B[(size_t)(n0+n)*KD + kt*BK + k4]);
                Bs[k4+0][n] = v.x; Bs[k4+1][n] = v.y; Bs[k4+2][n] = v.z; Bs[k4+3][n] = v.w;
            }
        }
        __syncthreads();
        #pragma unroll
        for (int kk8 = 0; kk8 < BK/8; kk8++){
            uint32_t af[2][4], bf[4][2];
            #pragma unroll
            for (int mt = 0; mt < 2; mt++){
                int m = wm*32 + mt*16;
                af[mt][0] = __float_as_uint(As[kk8*8 + t4    ][m + g    ]);
                af[mt][1] = __float_as_uint(As[kk8*8 + t4    ][m + g + 8]);
                af[mt][2] = __float_as_uint(As[kk8*8 + t4 + 4][m + g    ]);
                af[mt][3] = __float_as_uint(As[kk8*8 + t4 + 4][m + g + 8]);
            }
            #pragma unroll
            for (int nt = 0; nt < 4; nt++){
                int n = wn*32 + nt*8 + g;
                bf[nt][0] = __float_as_uint(Bs[kk8*8 + t4    ][n]);
                bf[nt][1] = __float_as_uint(Bs[kk8*8 + t4 + 4][n]);
            }
            #pragma unroll
            for (int mt = 0; mt < 2; mt++)
                #pragma unroll
                for (int nt = 0; nt < 4; nt++)
                    mma_tf32(acc[mt][nt], af[mt], bf[nt]);
        }
        __syncthreads();
    }
    #pragma unroll
    for (int mt = 0; mt < 2; mt++)
        #pragma unroll
        for (int nt = 0; nt < 4; nt++)
            #pragma unroll
            for (int e = 0; e < 4; e++){
                int r = m0 + wm*32 + mt*16 + g + ((e & 2) ? 8 : 0);
                int c = n0 + wn*32 + nt*8 + t4*2 + (e & 1);
                epi(kb, r, c, acc[mt][nt][e]);
            }
}

// ---------------- GCN GEMM: C[k] = A_bin[k](4096x4096) @ S[k](4096x256), k fused ----------------
// adj read once (k-interleaved int32 -> u8 in smem). Epilogue applies
// dinv_i * acc + dinv_i^2 * xw_i + gnn_b, stores tf32-rounded gnn_out.
__global__ void __launch_bounds__(256) gemm_gcn(const int* __restrict__ adj,
                                                const float* __restrict__ gnn_b)
{
    constexpr int BM = 128, BN = 64, BK = 32;
    __shared__ unsigned char Au[KG][BK][BM+4];
    __shared__ float Bs[KG][BK][BN+4];

    int m0 = blockIdx.y*BM;
    int n0 = blockIdx.x*BN;
    int tid = threadIdx.x, lane = tid & 31, wid = tid >> 5;
    int wm = wid & 3, wn = wid >> 2;
    int g = lane >> 2, t4 = lane & 3;

    float acc[KG][2][4][4];
    #pragma unroll
    for (int kk = 0; kk < KG; kk++)
        #pragma unroll
        for (int a = 0; a < 2; a++)
            #pragma unroll
            for (int b = 0; b < 4; b++)
                #pragma unroll
                for (int e = 0; e < 4; e++) acc[kk][a][b][e] = 0.f;

    for (int jt = 0; jt < NN/BK; jt++){
        // adj tile: rows m0..m0+127, j in [jt*32, jt*32+32), all 3 k (96 ints/row)
        #pragma unroll
        for (int it = 0; it < 12; it++){
            int idx = tid + it*256;
            int row = idx/24, q = idx - row*24;
            const int4* p = reinterpret_cast<const int4*>(
                adj + ((size_t)(m0+row)*NN + jt*BK)*KG);
            int4 v = p[q];
            int o = q*4;
            int o1 = o+1, o2 = o+2, o3 = o+3;
            Au[o  % 3][o  / 3][row] = (unsigned char)(v.x != 0);
            Au[o1 % 3][o1 / 3][row] = (unsigned char)(v.y != 0);
            Au[o2 % 3][o2 / 3][row] = (unsigned char)(v.z != 0);
            Au[o3 % 3][o3 / 3][row] = (unsigned char)(v.w != 0);
        }
        // S tiles for all k
        #pragma unroll
        for (int it = 0; it < 6; it++){
            int idx = tid + it*256;
            int kk = idx >> 9;
            int rem = idx & 511;
            int jj = rem >> 4, c4 = (rem & 15)*4;
            float4 v = *reinterpret_cast<const float4*>(
                &g_s[((size_t)kk*NN + jt*BK + jj)*HD + n0 + c4]);
            *reinterpret_cast<float4*>(&Bs[kk][jj][c4]) = v;
        }
        __syncthreads();
        #pragma unroll
        for (int kk8 = 0; kk8 < BK/8; kk8++){
            #pragma unroll
            for (int kk = 0; kk < KG; kk++){
                uint32_t af[2][4], bf[4][2];
                #pragma unroll
                for (int mt = 0; mt < 2; mt++){
                    int m = wm*32 + mt*16;
                    af[mt][0] = __float_as_uint((float)Au[kk][kk8*8 + t4    ][m + g    ]);
                    af[mt][1] = __float_as_uint((float)Au[kk][kk8*8 + t4    ][m + g + 8]);
                    af[mt][2] = __float_as_uint((float)Au[kk][kk8*8 + t4 + 4][m + g    ]);
                    af[mt][3] = __float_as_uint((float)Au[kk][kk8*8 + t4 + 4][m + g + 8]);
                }
                #pragma unroll
                for (int nt = 0; nt < 4; nt++){
                    int n = wn*32 + nt*8 + g;
                    bf[nt][0] = __float_as_uint(Bs[kk][kk8*8 + t4    ][n]);
                    bf[nt][1] = __float_as_uint(Bs[kk][kk8*8 + t4 + 4][n]);
                }
                #pragma unroll
                for (int mt = 0; mt < 2; mt++)
                    #pragma unroll
                    for (int nt = 0; nt < 4; nt++)
                        mma_tf32(acc[kk][mt][nt], af[mt], bf[nt]);
            }
        }
        __syncthreads();
    }
    #pragma unroll
    for (int kk = 0; kk < KG; kk++)
        #pragma unroll
        for (int mt = 0; mt < 2; mt++)
            #pragma unroll
            for (int nt = 0; nt < 4; nt++)
                #pragma unroll
                for (int e = 0; e < 4; e++){
                    int r = m0 + wm*32 + mt*16 + g + ((e & 2) ? 8 : 0);
                    int c = n0 + wn*32 + nt*8 + t4*2 + (e & 1);
                    float di = g_dinv[kk*NN + r];
                    float v = di*acc[kk][mt][nt][e]
                            + di*di*g_xw[((size_t)kk*NN + r)*HD + c]
                            + gnn_b[kk*HD + c];
                    g_gnn[((size_t)kk*NN + r)*HD + c] = rna(v);
                }
}

// ---------------- LSTM pointwise ----------------
__global__ void __launch_bounds__(256) lstm_point(int first)
{
    int k = blockIdx.y;
    int e = blockIdx.x*256 + threadIdx.x;     // over NN*HD
    int r = e >> 8, j = e & 255;
    size_t go = ((size_t)k*NN + r)*G4 + j;
    const float* gs = first ? g_xtp : g_gates;
    float gi = gs[go], gf = gs[go + 256], gg = gs[go + 512], goo = gs[go + 768];
    size_t hi = (size_t)k*NN*HD + e;
    float c_old = first ? 0.f : g_c[hi];
    float cn = sigf(gf)*c_old + sigf(gi)*tanhf_(gg);
    float hn = sigf(goo)*tanhf_(cn);
    g_c[hi] = cn;
    g_h[hi] = rna(hn);
}

// ---------------- final: pred + res_z_bar ----------------
__global__ void __launch_bounds__(256) final_out(const float* __restrict__ x,
                                                 float* __restrict__ out)
{
    int idx = blockIdx.x*256 + threadIdx.x;   // over NN*FD
    int f = idx & 255;
    bool sl = (f >= 10) && (f < FD - 3);      // START=10, F_DIM-END=253
    float xv = x[idx];
    float d0 = g_delta[idx];
    float d1 = g_delta[(size_t)NN*FD + idx];
    float d2 = g_delta[(size_t)2*NN*FD + idx];
    float z0 = xv + d0, z1 = xv + d1, z2 = xv + d2;
    if (sl){ z0 = sigf(z0); z1 = sigf(z1); z2 = sigf(z2); }
    size_t zb = (size_t)NN*FD + (size_t)idx*3;
    out[zb + 0] = z0; out[zb + 1] = z1; out[zb + 2] = z2;
    float dm = (d0 + d1 + d2) * (1.f/3.f);
    float p = xv + dm;
    if (sl) p = sigf(p);
    out[idx] = p;
}

// ---------------- launch ----------------
extern "C" void kernel_launch(void* const* d_in, const int* in_sizes, int n_in,
                              void* d_out, int out_size)
{
    const float* x     = (const float*)d_in[0];
    const float* gnn_w = (const float*)d_in[1];
    const float* gnn_b = (const float*)d_in[2];
    const float* w_ih  = (const float*)d_in[3];
    const float* w_hh  = (const float*)d_in[4];
    const float* b_ih  = (const float*)d_in[5];
    const float* b_hh  = (const float*)d_in[6];
    const float* fc_w  = (const float*)d_in[7];
    const float* fc_b  = (const float*)d_in[8];
    const int*   adj   = (const int*)d_in[9];
    float* out = (float*)d_out;

    (void)in_sizes; (void)n_in; (void)out_size;

    prep_round<<<512, 256>>>(x, gnn_w, w_ih, w_hh, fc_w);
    adj_pass<<<NN, 256>>>(adj, out + (size_t)NN*FD*(1 + KG));
    // xw = x @ gnn_w[k]; store exact xw and s = rna(dinv * xw)
    gemm_k256<HD, false, EpiXW><<<dim3(HD/64, NN/128, KG), 256>>>(0, 0, EpiXW{});
    // gnn_out (all k fused, adj read once)
    gemm_gcn<<<dim3(HD/64, NN/128), 256>>>(adj, gnn_b);
    // xtp = gnn_out @ w_ih^T + b_ih + b_hh
    gemm_k256<G4, true, EpiXTP><<<dim3(G4/64, NN/128, KG), 256>>>(1, 1, EpiXTP{b_ih, b_hh});
    // step 1: h0 = 0 -> gates = xtp
    lstm_point<<<dim3(NN*HD/256, KG), 256>>>(1);
    for (int t = 1; t < TST; t++){
        gemm_k256<G4, true, EpiGates><<<dim3(G4/64, NN/128, KG), 256>>>(2, 2, EpiGates{});
        lstm_point<<<dim3(NN*HD/256, KG), 256>>>(0);
    }
    // delta = tanh(h @ fc_w^T + fc_b)
    gemm_k256<FD, true, EpiFC><<<dim3(FD/64, NN/128, KG), 256>>>(2, 3, EpiFC{fc_b});
    final_out<<<NN*FD/256, 256>>>(x, out);
}

// round 4
// speedup vs baseline: 2.1924x; 2.1924x over previous
#include <cuda_runtime.h>
#include <cuda_bf16.h>
#include <cstdint>
#include <cstddef>

#define NN 4096
#define FD 256
#define HD 256
#define KG 3
#define G4 1024
#define TST 5

typedef __nv_bfloat16 bf16;
typedef __nv_bfloat162 bf162;

// ---------------- scratch (device globals) ----------------
static __device__ __align__(16) bf16 g_bx[NN*FD];
static __device__ __align__(16) bf16 g_bgw[KG*FD*HD];
static __device__ __align__(16) bf16 g_bwih[KG*G4*HD];
static __device__ __align__(16) bf16 g_bwhh[KG*G4*HD];
static __device__ __align__(16) bf16 g_bfcw[KG*FD*HD];
static __device__ __align__(16) bf16 g_a16[(size_t)KG*NN*NN];   // binarized adjacency planes
static __device__ __align__(16) bf16 g_s16[(size_t)KG*NN*HD];   // dinv_j * xw, bf16
static __device__ __align__(16) bf16 g_bgnn[(size_t)KG*NN*HD];  // gnn out bf16
static __device__ __align__(16) bf16 g_bh[(size_t)KG*NN*HD];    // lstm h bf16

static __device__ float g_dinv[KG*NN];
static __device__ float g_xw[(size_t)KG*NN*HD];
static __device__ float g_xtp[(size_t)KG*NN*G4];
static __device__ float g_gates[(size_t)KG*NN*G4];
static __device__ float g_c[(size_t)KG*NN*HD];
static __device__ float g_delta[(size_t)KG*NN*FD];

// ---------------- helpers ----------------
__device__ __forceinline__ float sigf(float x){
    x = fminf(fmaxf(x, -30.f), 30.f);
    return __fdividef(1.f, 1.f + __expf(-x));
}
__device__ __forceinline__ float tanhf_(float x){
    x = fminf(fmaxf(x, -15.f), 15.f);
    float e = __expf(2.f*x);
    return __fdividef(e - 1.f, e + 1.f);
}

__device__ __forceinline__ void mma16816(float* c, const uint32_t* a, const uint32_t* b){
    asm volatile(
        "mma.sync.aligned.m16n8k16.row.col.f32.bf16.bf16.f32 "
        "{%0,%1,%2,%3}, {%4,%5,%6,%7}, {%8,%9}, {%0,%1,%2,%3};"
        : "+f"(c[0]), "+f"(c[1]), "+f"(c[2]), "+f"(c[3])
        : "r"(a[0]), "r"(a[1]), "r"(a[2]), "r"(a[3]), "r"(b[0]), "r"(b[1]));
}
__device__ __forceinline__ void ldsm4(uint32_t& r0, uint32_t& r1, uint32_t& r2, uint32_t& r3, uint32_t a){
    asm volatile("ldmatrix.sync.aligned.m8n8.x4.shared.b16 {%0,%1,%2,%3}, [%4];"
        : "=r"(r0), "=r"(r1), "=r"(r2), "=r"(r3) : "r"(a));
}
__device__ __forceinline__ void ldsm4t(uint32_t& r0, uint32_t& r1, uint32_t& r2, uint32_t& r3, uint32_t a){
    asm volatile("ldmatrix.sync.aligned.m8n8.x4.trans.shared.b16 {%0,%1,%2,%3}, [%4];"
        : "=r"(r0), "=r"(r1), "=r"(r2), "=r"(r3) : "r"(a));
}
__device__ __forceinline__ void cpasync16(uint32_t dst, const void* src){
    asm volatile("cp.async.cg.shared.global [%0], [%1], 16;\n" :: "r"(dst), "l"(src));
}
#define SWZ(off) ((off) ^ (((off) >> 3) & 0x70))

// ---------------- prep: fp32 -> bf16 weights/inputs ----------------
__global__ void __launch_bounds__(256) prep_bf16(
    const float* __restrict__ x, const float* __restrict__ gw,
    const float* __restrict__ wih, const float* __restrict__ whh,
    const float* __restrict__ fcw)
{
    int i = blockIdx.x*blockDim.x + threadIdx.x;
    int stride = gridDim.x*blockDim.x;
    for (int t = i; t < NN*FD; t += stride)    g_bx[t]   = __float2bfloat16_rn(x[t]);
    for (int t = i; t < KG*FD*HD; t += stride) g_bgw[t]  = __float2bfloat16_rn(gw[t]);
    for (int t = i; t < KG*G4*HD; t += stride) g_bwih[t] = __float2bfloat16_rn(wih[t]);
    for (int t = i; t < KG*G4*HD; t += stride) g_bwhh[t] = __float2bfloat16_rn(whh[t]);
    for (int t = i; t < KG*FD*HD; t += stride) g_bfcw[t] = __float2bfloat16_rn(fcw[t]);
}

// ---------------- adj pass: passthrough + binarized bf16 planes + dinv ----------------
__global__ void __launch_bounds__(256) adj_pass(const int* __restrict__ adj,
                                                float* __restrict__ out_adj)
{
    int row = blockIdx.x;
    const int4* src = reinterpret_cast<const int4*>(adj + (size_t)row*NN*KG);
    float4* dst = reinterpret_cast<float4*>(out_adj + (size_t)row*NN*KG);
    int c0 = 0, c1 = 0, c2 = 0;
    #pragma unroll
    for (int it = 0; it < 4; it++){
        int jg = threadIdx.x + it*256;               // group of 4 j's
        int4 v0 = src[jg*3+0];
        int4 v1 = src[jg*3+1];
        int4 v2 = src[jg*3+2];
        dst[jg*3+0] = make_float4((float)v0.x,(float)v0.y,(float)v0.z,(float)v0.w);
        dst[jg*3+1] = make_float4((float)v1.x,(float)v1.y,(float)v1.z,(float)v1.w);
        dst[jg*3+2] = make_float4((float)v2.x,(float)v2.y,(float)v2.z,(float)v2.w);
        // k0 over j0..j3: o0,o3,o6,o9 ; k1: o1,o4,o7,o10 ; k2: o2,o5,o8,o11
        ushort4 b0, b1, b2;
        b0.x = v0.x ? 0x3F80 : 0; b0.y = v0.w ? 0x3F80 : 0;
        b0.z = v1.z ? 0x3F80 : 0; b0.w = v2.y ? 0x3F80 : 0;
        b1.x = v0.y ? 0x3F80 : 0; b1.y = v1.x ? 0x3F80 : 0;
        b1.z = v1.w ? 0x3F80 : 0; b1.w = v2.z ? 0x3F80 : 0;
        b2.x = v0.z ? 0x3F80 : 0; b2.y = v1.y ? 0x3F80 : 0;
        b2.z = v2.x ? 0x3F80 : 0; b2.w = v2.w ? 0x3F80 : 0;
        size_t base = (size_t)row*NN + jg*4;
        *reinterpret_cast<ushort4*>(&g_a16[base])                     = b0;
        *reinterpret_cast<ushort4*>(&g_a16[(size_t)NN*NN + base])     = b1;
        *reinterpret_cast<ushort4*>(&g_a16[(size_t)2*NN*NN + base])   = b2;
        c0 += (b0.x?1:0) + (b0.y?1:0) + (b0.z?1:0) + (b0.w?1:0);
        c1 += (b1.x?1:0) + (b1.y?1:0) + (b1.z?1:0) + (b1.w?1:0);
        c2 += (b2.x?1:0) + (b2.y?1:0) + (b2.z?1:0) + (b2.w?1:0);
    }
    __shared__ int sm[3];
    if (threadIdx.x < 3) sm[threadIdx.x] = 0;
    __syncthreads();
    c0 = __reduce_add_sync(0xffffffffu, c0);
    c1 = __reduce_add_sync(0xffffffffu, c1);
    c2 = __reduce_add_sync(0xffffffffu, c2);
    if ((threadIdx.x & 31) == 0){
        atomicAdd(&sm[0], c0); atomicAdd(&sm[1], c1); atomicAdd(&sm[2], c2);
    }
    __syncthreads();
    if (threadIdx.x < 3){
        float deg = (float)(sm[threadIdx.x] + 1);     // + self-loop
        g_dinv[threadIdx.x*NN + row] = rsqrtf(deg);
    }
}

// ---------------- epilogue functors (pairwise: columns c, c+1) ----------------
struct EpiXW {
    __device__ void operator()(int k, int r, int c, float v0, float v1) const {
        size_t i = ((size_t)k*NN + r)*HD + c;
        g_xw[i] = v0; g_xw[i+1] = v1;
        float di = g_dinv[k*NN + r];
        *reinterpret_cast<bf162*>(&g_s16[i]) = __floats2bfloat162_rn(di*v0, di*v1);
    }
};
struct EpiGCN {
    const float* gb;
    __device__ void operator()(int k, int r, int c, float v0, float v1) const {
        float di = g_dinv[k*NN + r];
        size_t i = ((size_t)k*NN + r)*HD + c;
        float o0 = di*v0 + di*di*g_xw[i]   + gb[k*HD + c];
        float o1 = di*v1 + di*di*g_xw[i+1] + gb[k*HD + c + 1];
        *reinterpret_cast<bf162*>(&g_bgnn[i]) = __floats2bfloat162_rn(o0, o1);
    }
};
struct EpiXTP {
    const float* bih; const float* bhh;
    __device__ void operator()(int k, int r, int c, float v0, float v1) const {
        size_t i = ((size_t)k*NN + r)*G4 + c;
        g_xtp[i]   = v0 + bih[k*G4 + c]     + bhh[k*G4 + c];
        g_xtp[i+1] = v1 + bih[k*G4 + c + 1] + bhh[k*G4 + c + 1];
    }
};
struct EpiGates {
    __device__ void operator()(int k, int r, int c, float v0, float v1) const {
        size_t i = ((size_t)k*NN + r)*G4 + c;
        g_gates[i]   = v0 + g_xtp[i];
        g_gates[i+1] = v1 + g_xtp[i+1];
    }
};
struct EpiFC {
    const float* fcb;
    __device__ void operator()(int k, int r, int c, float v0, float v1) const {
        size_t i = ((size_t)k*NN + r)*FD + c;
        g_delta[i]   = tanhf_(v0 + fcb[k*FD + c]);
        g_delta[i+1] = tanhf_(v1 + fcb[k*FD + c + 1]);
    }
};

// ---------------- bf16 GEMM: BM=128, BN=64, BK=64, double-buffered cp.async ----------------
// A row-major [M][KD]. B: KMAJOR -> global [KD][NC] (smem k-rows, ldmatrix.trans);
// else NMAJOR -> global [NC][KD] (smem n-rows, plain ldmatrix).
template<int KD, int NC, bool KMAJOR, bool GORD, class Epi>
__global__ void __launch_bounds__(256, 2) gemm_bf(int a_sel, int b_sel, Epi epi)
{
    __shared__ bf16 As[2][128*64];
    __shared__ bf16 Bs[2][64*64];

    int n0, m0, kb;
    if (GORD){ n0 = blockIdx.x*64; kb = blockIdx.y; m0 = blockIdx.z*128; }
    else     { n0 = blockIdx.x*64; m0 = blockIdx.y*128; kb = blockIdx.z; }

    const bf16* A;
    if (a_sel == 0)      A = g_bx;
    else if (a_sel == 1) A = g_bgnn + (size_t)kb*NN*HD;
    else if (a_sel == 2) A = g_bh   + (size_t)kb*NN*HD;
    else                 A = g_a16  + (size_t)kb*NN*NN;

    const bf16* B;
    if (b_sel == 0)      B = g_bgw  + (size_t)kb*FD*HD;
    else if (b_sel == 1) B = g_s16  + (size_t)kb*NN*HD;
    else if (b_sel == 2) B = g_bwih + (size_t)kb*G4*HD;
    else if (b_sel == 3) B = g_bwhh + (size_t)kb*G4*HD;
    else                 B = g_bfcw + (size_t)kb*FD*HD;

    int tid = threadIdx.x, lane = tid & 31, wid = tid >> 5;
    int wm = wid & 3, wn = wid >> 2;              // 4 m-warps x 2 n-warps; warp tile 32x32
    uint32_t asB[2], bsB[2];
    asB[0] = (uint32_t)__cvta_generic_to_shared(&As[0][0]);
    asB[1] = (uint32_t)__cvta_generic_to_shared(&As[1][0]);
    bsB[0] = (uint32_t)__cvta_generic_to_shared(&Bs[0][0]);
    bsB[1] = (uint32_t)__cvta_generic_to_shared(&Bs[1][0]);

    float acc[2][4][4];
    #pragma unroll
    for (int a = 0; a < 2; a++)
        #pragma unroll
        for (int b = 0; b < 4; b++)
            #pragma unroll
            for (int e = 0; e < 4; e++) acc[a][b][e] = 0.f;

    constexpr int KT = KD/64;

    auto load_tile = [&](int kt, int s){
        #pragma unroll
        for (int i = 0; i < 4; i++){
            int idx = tid + i*256;
            int row = idx >> 3, c = idx & 7;
            int off = row*128 + c*16;
            cpasync16(asB[s] + SWZ(off), A + (size_t)(m0+row)*KD + kt*64 + c*8);
        }
        #pragma unroll
        for (int i = 0; i < 2; i++){
            int idx = tid + i*256;
            int row = idx >> 3, c = idx & 7;
            int off = row*128 + c*16;
            const bf16* src = KMAJOR
                ? B + (size_t)(kt*64 + row)*NC + n0 + c*8
                : B + (size_t)(n0 + row)*KD + kt*64 + c*8;
            cpasync16(bsB[s] + SWZ(off), src);
        }
        asm volatile("cp.async.commit_group;\n" ::: "memory");
    };

    load_tile(0, 0);
    int lr = lane & 15, lc = lane >> 4;
    for (int kt = 0; kt < KT; kt++){
        if (kt + 1 < KT){
            load_tile(kt+1, (kt+1)&1);
            asm volatile("cp.async.wait_group 1;\n" ::: "memory");
        } else {
            asm volatile("cp.async.wait_group 0;\n" ::: "memory");
        }
        __syncthreads();
        int s = kt & 1;
        #pragma unroll
        for (int k16 = 0; k16 < 4; k16++){
            uint32_t a[2][4];
            #pragma unroll
            for (int mt = 0; mt < 2; mt++){
                int row = wm*32 + mt*16 + lr;
                int off = row*128 + k16*32 + lc*16;
                ldsm4(a[mt][0], a[mt][1], a[mt][2], a[mt][3], asB[s] + SWZ(off));
            }
            uint32_t b[4][2];
            #pragma unroll
            for (int p = 0; p < 2; p++){
                uint32_t r0, r1, r2, r3;
                if (KMAJOR){
                    int row = k16*16 + lr;
                    int off = row*128 + (wn*32 + p*16 + lc*8)*2;
                    ldsm4t(r0, r1, r2, r3, bsB[s] + SWZ(off));
                    b[p*2  ][0] = r0; b[p*2  ][1] = r1;
                    b[p*2+1][0] = r2; b[p*2+1][1] = r3;
                } else {
                    int row = wn*32 + p*16 + lr;
                    int off = row*128 + k16*32 + lc*16;
                    ldsm4(r0, r1, r2, r3, bsB[s] + SWZ(off));
                    b[p*2  ][0] = r0; b[p*2  ][1] = r2;
                    b[p*2+1][0] = r1; b[p*2+1][1] = r3;
                }
            }
            #pragma unroll
            for (int mt = 0; mt < 2; mt++)
                #pragma unroll
                for (int nt = 0; nt < 4; nt++)
                    mma16816(acc[mt][nt], a[mt], b[nt]);
        }
        __syncthreads();
    }

    int g = lane >> 2, t4 = lane & 3;
    #pragma unroll
    for (int mt = 0; mt < 2; mt++)
        #pragma unroll
        for (int nt = 0; nt < 4; nt++){
            int r = m0 + wm*32 + mt*16 + g;
            int c = n0 + wn*32 + nt*8 + t4*2;
            epi(kb, r,     c, acc[mt][nt][0], acc[mt][nt][1]);
            epi(kb, r + 8, c, acc[mt][nt][2], acc[mt][nt][3]);
        }
}

// ---------------- LSTM pointwise ----------------
__global__ void __launch_bounds__(256) lstm_point(int first)
{
    int k = blockIdx.y;
    int e = blockIdx.x*256 + threadIdx.x;     // over NN*HD
    int r = e >> 8, j = e & 255;
    size_t go = ((size_t)k*NN + r)*G4 + j;
    const float* gs = first ? g_xtp : g_gates;
    float gi = gs[go], gf = gs[go + 256], gg = gs[go + 512], goo = gs[go + 768];
    size_t hi = (size_t)k*NN*HD + e;
    float c_old = first ? 0.f : g_c[hi];
    float cn = sigf(gf)*c_old + sigf(gi)*tanhf_(gg);
    float hn = sigf(goo)*tanhf_(cn);
    g_c[hi] = cn;
    g_bh[hi] = __float2bfloat16_rn(hn);
}

// ---------------- final: pred + res_z_bar ----------------
__global__ void __launch_bounds__(256) final_out(const float* __restrict__ x,
                                                 float* __restrict__ out)
{
    int idx = blockIdx.x*256 + threadIdx.x;   // over NN*FD
    int f = idx & 255;
    bool sl = (f >= 10) && (f < FD - 3);      // START=10, F_DIM-END=253
    float xv = x[idx];
    float d0 = g_delta[idx];
    float d1 = g_delta[(size_t)NN*FD + idx];
    float d2 = g_delta[(size_t)2*NN*FD + idx];
    float z0 = xv + d0, z1 = xv + d1, z2 = xv + d2;
    if (sl){ z0 = sigf(z0); z1 = sigf(z1); z2 = sigf(z2); }
    size_t zb = (size_t)NN*FD + (size_t)idx*3;
    out[zb + 0] = z0; out[zb + 1] = z1; out[zb + 2] = z2;
    float dm = (d0 + d1 + d2) * (1.f/3.f);
    float p = xv + dm;
    if (sl) p = sigf(p);
    out[idx] = p;
}

// ---------------- launch ----------------
extern "C" void kernel_launch(void* const* d_in, const int* in_sizes, int n_in,
                              void* d_out, int out_size)
{
    const float* x     = (const float*)d_in[0];
    const float* gnn_w = (const float*)d_in[1];
    const float* gnn_b = (const float*)d_in[2];
    const float* w_ih  = (const float*)d_in[3];
    const float* w_hh  = (const float*)d_in[4];
    const float* b_ih  = (const float*)d_in[5];
    const float* b_hh  = (const float*)d_in[6];
    const float* fc_w  = (const float*)d_in[7];
    const float* fc_b  = (const float*)d_in[8];
    const int*   adj   = (const int*)d_in[9];
    float* out = (float*)d_out;

    (void)in_sizes; (void)n_in; (void)out_size;

    prep_bf16<<<512, 256>>>(x, gnn_w, w_ih, w_hh, fc_w);
    adj_pass<<<NN, 256>>>(adj, out + (size_t)NN*FD*(1 + KG));

    // xw = x @ gnn_w[k] -> g_xw fp32 + g_s16 = bf16(dinv * xw)
    gemm_bf<256, 256, true,  false, EpiXW><<<dim3(4, 32, 3), 256>>>(0, 0, EpiXW{});
    // gnn_out[k] = dinv_i * (Abin[k] @ s[k]) + dinv_i^2 * xw + b   (grid: n,k,m for L2 A reuse)
    gemm_bf<4096, 256, true, true,  EpiGCN><<<dim3(4, 3, 32), 256>>>(3, 1, EpiGCN{gnn_b});
    // xtp = gnn_out @ w_ih^T + b_ih + b_hh
    gemm_bf<256, 1024, false, false, EpiXTP><<<dim3(16, 32, 3), 256>>>(1, 2, EpiXTP{b_ih, b_hh});
    // step 1: h0 = 0 -> gates = xtp
    lstm_point<<<dim3(NN*HD/256, KG), 256>>>(1);
    for (int t = 1; t < TST; t++){
        gemm_bf<256, 1024, false, false, EpiGates><<<dim3(16, 32, 3), 256>>>(2, 3, EpiGates{});
        lstm_point<<<dim3(NN*HD/256, KG), 256>>>(0);
    }
    // delta = tanh(h @ fc_w^T + fc_b)
    gemm_bf<256, 256, false, false, EpiFC><<<dim3(4, 32, 3), 256>>>(2, 4, EpiFC{fc_b});
    final_out<<<NN*FD/256, 256>>>(x, out);
}

// round 6
// speedup vs baseline: 2.9998x; 1.3683x over previous
#include <cuda_runtime.h>
#include <cuda_bf16.h>
#include <cstdint>
#include <cstddef>

#define NN 4096
#define FD 256
#define HD 256
#define KG 3
#define G4 1024
#define TST 5

typedef __nv_bfloat16 bf16;
typedef __nv_bfloat162 bf162;

// ---------------- scratch (device globals) ----------------
static __device__ __align__(16) bf16 g_bx[NN*FD];
static __device__ __align__(16) bf16 g_bgw[KG*FD*HD];
static __device__ __align__(16) bf16 g_bwihp[KG*G4*HD];   // gate-permuted
static __device__ __align__(16) bf16 g_bwhhp[KG*G4*HD];   // gate-permuted
static __device__ __align__(16) bf16 g_bfcw[KG*FD*HD];
static __device__ __align__(16) bf16 g_a16[(size_t)KG*NN*NN];   // binarized adjacency planes (+I on diag)
static __device__ __align__(16) bf16 g_s16[(size_t)KG*NN*HD];   // dinv_j * xw, bf16
static __device__ __align__(16) bf16 g_bgnn[(size_t)KG*NN*HD];  // gnn out bf16
static __device__ __align__(16) bf16 g_bh[(size_t)KG*NN*HD];    // lstm h bf16
static __device__ __align__(16) bf16 g_xtp16[(size_t)KG*NN*G4]; // x-part of gates, permuted, bf16

static __device__ float g_dinv[KG*NN];
static __device__ float g_bcomb[KG*G4];                   // b_ih + b_hh, permuted
static __device__ float g_c[(size_t)KG*NN*HD];
static __device__ float g_delta[(size_t)KG*NN*FD];

// ---------------- helpers ----------------
__device__ __forceinline__ float sigf(float x){
    x = fminf(fmaxf(x, -30.f), 30.f);
    return __fdividef(1.f, 1.f + __expf(-x));
}
__device__ __forceinline__ float tanhf_(float x){
    x = fminf(fmaxf(x, -15.f), 15.f);
    float e = __expf(2.f*x);
    return __fdividef(e - 1.f, e + 1.f);
}

__device__ __forceinline__ void mma16816(float* c, const uint32_t* a, const uint32_t* b){
    asm volatile(
        "mma.sync.aligned.m16n8k16.row.col.f32.bf16.bf16.f32 "
        "{%0,%1,%2,%3}, {%4,%5,%6,%7}, {%8,%9}, {%0,%1,%2,%3};"
        : "+f"(c[0]), "+f"(c[1]), "+f"(c[2]), "+f"(c[3])
        : "r"(a[0]), "r"(a[1]), "r"(a[2]), "r"(a[3]), "r"(b[0]), "r"(b[1]));
}
__device__ __forceinline__ void ldsm4(uint32_t& r0, uint32_t& r1, uint32_t& r2, uint32_t& r3, uint32_t a){
    asm volatile("ldmatrix.sync.aligned.m8n8.x4.shared.b16 {%0,%1,%2,%3}, [%4];"
        : "=r"(r0), "=r"(r1), "=r"(r2), "=r"(r3) : "r"(a));
}
__device__ __forceinline__ void ldsm4t(uint32_t& r0, uint32_t& r1, uint32_t& r2, uint32_t& r3, uint32_t a){
    asm volatile("ldmatrix.sync.aligned.m8n8.x4.trans.shared.b16 {%0,%1,%2,%3}, [%4];"
        : "=r"(r0), "=r"(r1), "=r"(r2), "=r"(r3) : "r"(a));
}
__device__ __forceinline__ void cpasync16(uint32_t dst, const void* src){
    asm volatile("cp.async.cg.shared.global [%0], [%1], 16;\n" :: "r"(dst), "l"(src));
}
#define SWZ(off) ((off) ^ (((off) >> 3) & 0x70))

// ---------------- prep: bf16 conversions + gate permutation ----------------
// permuted gate index: cp = (u>>3)*32 + gate*8 + (u&7); inverse: gate=(cp>>3)&3, u=((cp>>5)<<3)|(cp&7)
__global__ void __launch_bounds__(256) prep_bf16(
    const float* __restrict__ x, const float* __restrict__ gw,
    const float* __restrict__ wih, const float* __restrict__ whh,
    const float* __restrict__ bih, const float* __restrict__ bhh,
    const float* __restrict__ fcw)
{
    int i = blockIdx.x*blockDim.x + threadIdx.x;
    int stride = gridDim.x*blockDim.x;
    for (int t = i; t < NN*FD; t += stride)    g_bx[t]   = __float2bfloat16_rn(x[t]);
    for (int t = i; t < KG*FD*HD; t += stride) g_bgw[t]  = __float2bfloat16_rn(gw[t]);
    for (int t = i; t < KG*FD*HD; t += stride) g_bfcw[t] = __float2bfloat16_rn(fcw[t]);
    for (int t = i; t < KG*G4*HD; t += stride){
        int k = t / (G4*HD);
        int rem = t - k*(G4*HD);
        int cp = rem >> 8, h = rem & 255;
        int gate = (cp >> 3) & 3;
        int u = ((cp >> 5) << 3) | (cp & 7);
        int orig = k*G4*HD + (gate*256 + u)*HD + h;
        g_bwihp[t] = __float2bfloat16_rn(wih[orig]);
        g_bwhhp[t] = __float2bfloat16_rn(whh[orig]);
    }
    for (int t = i; t < KG*G4; t += stride){
        int k = t >> 10, cp = t & 1023;
        int gate = (cp >> 3) & 3;
        int u = ((cp >> 5) << 3) | (cp & 7);
        g_bcomb[t] = bih[k*G4 + gate*256 + u] + bhh[k*G4 + gate*256 + u];
    }
}

// ---------------- adj pass: passthrough + binarized bf16 planes (+I) + dinv ----------------
__global__ void __launch_bounds__(256) adj_pass(const int* __restrict__ adj,
                                                float* __restrict__ out_adj)
{
    int row = blockIdx.x;
    const int4* src = reinterpret_cast<const int4*>(adj + (size_t)row*NN*KG);
    float4* dst = reinterpret_cast<float4*>(out_adj + (size_t)row*NN*KG);
    int c0 = 0, c1 = 0, c2 = 0;
    #pragma unroll
    for (int it = 0; it < 4; it++){
        int jg = threadIdx.x + it*256;               // group of 4 j's
        int4 v0 = src[jg*3+0];
        int4 v1 = src[jg*3+1];
        int4 v2 = src[jg*3+2];
        dst[jg*3+0] = make_float4((float)v0.x,(float)v0.y,(float)v0.z,(float)v0.w);
        dst[jg*3+1] = make_float4((float)v1.x,(float)v1.y,(float)v1.z,(float)v1.w);
        dst[jg*3+2] = make_float4((float)v2.x,(float)v2.y,(float)v2.z,(float)v2.w);
        ushort4 b0, b1, b2;
        b0.x = v0.x ? 0x3F80 : 0; b0.y = v0.w ? 0x3F80 : 0;
        b0.z = v1.z ? 0x3F80 : 0; b0.w = v2.y ? 0x3F80 : 0;
        b1.x = v0.y ? 0x3F80 : 0; b1.y = v1.x ? 0x3F80 : 0;
        b1.z = v1.w ? 0x3F80 : 0; b1.w = v2.z ? 0x3F80 : 0;
        b2.x = v0.z ? 0x3F80 : 0; b2.y = v1.y ? 0x3F80 : 0;
        b2.z = v2.x ? 0x3F80 : 0; b2.w = v2.w ? 0x3F80 : 0;
        size_t base = (size_t)row*NN + jg*4;
        *reinterpret_cast<ushort4*>(&g_a16[base])                   = b0;
        *reinterpret_cast<ushort4*>(&g_a16[(size_t)NN*NN + base])   = b1;
        *reinterpret_cast<ushort4*>(&g_a16[(size_t)2*NN*NN + base]) = b2;
        c0 += (b0.x?1:0) + (b0.y?1:0) + (b0.z?1:0) + (b0.w?1:0);
        c1 += (b1.x?1:0) + (b1.y?1:0) + (b1.z?1:0) + (b1.w?1:0);
        c2 += (b2.x?1:0) + (b2.y?1:0) + (b2.z?1:0) + (b2.w?1:0);
    }
    __shared__ int sm[3];
    if (threadIdx.x < 3) sm[threadIdx.x] = 0;
    __syncthreads();
    c0 = __reduce_add_sync(0xffffffffu, c0);
    c1 = __reduce_add_sync(0xffffffffu, c1);
    c2 = __reduce_add_sync(0xffffffffu, c2);
    if ((threadIdx.x & 31) == 0){
        atomicAdd(&sm[0], c0); atomicAdd(&sm[1], c1); atomicAdd(&sm[2], c2);
    }
    __syncthreads();
    if (threadIdx.x < 3){
        // self-loop on diagonal: A_hat = A_bin + I  (0/1 -> 1/2, exact in bf16)
        size_t d = (size_t)threadIdx.x*NN*NN + (size_t)row*NN + row;
        g_a16[d] = __float2bfloat16_rn(__bfloat162float(g_a16[d]) + 1.0f);
        float deg = (float)(sm[threadIdx.x] + 1);
        g_dinv[threadIdx.x*NN + row] = rsqrtf(deg);
    }
}

// ---------------- epilogue functors (pairwise: columns c, c+1) ----------------
struct EpiXW {
    __device__ void operator()(int k, int r, int c, float v0, float v1) const {
        float di = g_dinv[k*NN + r];
        size_t i = ((size_t)k*NN + r)*HD + c;
        *reinterpret_cast<bf162*>(&g_s16[i]) = __floats2bfloat162_rn(di*v0, di*v1);
    }
};
struct EpiGCN {
    const float* gb;
    __device__ void operator()(int k, int r, int c, float v0, float v1) const {
        float di = g_dinv[k*NN + r];
        size_t i = ((size_t)k*NN + r)*HD + c;
        *reinterpret_cast<bf162*>(&g_bgnn[i]) =
            __floats2bfloat162_rn(di*v0 + gb[k*HD + c], di*v1 + gb[k*HD + c + 1]);
    }
};
struct EpiFC {
    const float* fcb;
    __device__ void operator()(int k, int r, int c, float v0, float v1) const {
        size_t i = ((size_t)k*NN + r)*FD + c;
        g_delta[i]   = tanhf_(v0 + fcb[k*FD + c]);
        g_delta[i+1] = tanhf_(v1 + fcb[k*FD + c + 1]);
    }
};

// ---------------- bf16 GEMM: BM=128, BN=64, BK=64, double-buffered cp.async ----------------
template<int KD, int NC, bool KMAJOR, bool GORD, class Epi>
__global__ void __launch_bounds__(256, 2) gemm_bf(int a_sel, int b_sel, Epi epi)
{
    __shared__ bf16 As[2][128*64];
    __shared__ bf16 Bs[2][64*64];

    int n0, m0, kb;
    if (GORD){ n0 = blockIdx.x*64; kb = blockIdx.y; m0 = blockIdx.z*128; }
    else     { n0 = blockIdx.x*64; m0 = blockIdx.y*128; kb = blockIdx.z; }

    const bf16* A;
    if (a_sel == 0)      A = g_bx;
    else if (a_sel == 2) A = g_bh   + (size_t)kb*NN*HD;
    else                 A = g_a16  + (size_t)kb*NN*NN;

    const bf16* B;
    if (b_sel == 0)      B = g_bgw  + (size_t)kb*FD*HD;
    else if (b_sel == 1) B = g_s16  + (size_t)kb*NN*HD;
    else                 B = g_bfcw + (size_t)kb*FD*HD;

    int tid = threadIdx.x, lane = tid & 31, wid = tid >> 5;
    int wm = wid & 3, wn = wid >> 2;
    uint32_t asB[2], bsB[2];
    asB[0] = (uint32_t)__cvta_generic_to_shared(&As[0][0]);
    asB[1] = (uint32_t)__cvta_generic_to_shared(&As[1][0]);
    bsB[0] = (uint32_t)__cvta_generic_to_shared(&Bs[0][0]);
    bsB[1] = (uint32_t)__cvta_generic_to_shared(&Bs[1][0]);

    float acc[2][4][4];
    #pragma unroll
    for (int a = 0; a < 2; a++)
        #pragma unroll
        for (int b = 0; b < 4; b++)
            #pragma unroll
            for (int e = 0; e < 4; e++) acc[a][b][e] = 0.f;

    constexpr int KT = KD/64;

    auto load_tile = [&](int kt, int s){
        #pragma unroll
        for (int i = 0; i < 4; i++){
            int idx = tid + i*256;
            int row = idx >> 3, c = idx & 7;
            int off = row*128 + c*16;
            cpasync16(asB[s] + SWZ(off), A + (size_t)(m0+row)*KD + kt*64 + c*8);
        }
        #pragma unroll
        for (int i = 0; i < 2; i++){
            int idx = tid + i*256;
            int row = idx >> 3, c = idx & 7;
            int off = row*128 + c*16;
            const bf16* src = KMAJOR
                ? B + (size_t)(kt*64 + row)*NC + n0 + c*8
                : B + (size_t)(n0 + row)*KD + kt*64 + c*8;
            cpasync16(bsB[s] + SWZ(off), src);
        }
        asm volatile("cp.async.commit_group;\n" ::: "memory");
    };

    load_tile(0, 0);
    int lr = lane & 15, lc = lane >> 4;
    for (int kt = 0; kt < KT; kt++){
        if (kt + 1 < KT){
            load_tile(kt+1, (kt+1)&1);
            asm volatile("cp.async.wait_group 1;\n" ::: "memory");
        } else {
            asm volatile("cp.async.wait_group 0;\n" ::: "memory");
        }
        __syncthreads();
        int s = kt & 1;
        #pragma unroll
        for (int k16 = 0; k16 < 4; k16++){
            uint32_t a[2][4];
            #pragma unroll
            for (int mt = 0; mt < 2; mt++){
                int row = wm*32 + mt*16 + lr;
                int off = row*128 + k16*32 + lc*16;
                ldsm4(a[mt][0], a[mt][1], a[mt][2], a[mt][3], asB[s] + SWZ(off));
            }
            uint32_t b[4][2];
            #pragma unroll
            for (int p = 0; p < 2; p++){
                uint32_t r0, r1, r2, r3;
                if (KMAJOR){
                    int row = k16*16 + lr;
                    int off = row*128 + (wn*32 + p*16 + lc*8)*2;
                    ldsm4t(r0, r1, r2, r3, bsB[s] + SWZ(off));
                    b[p*2  ][0] = r0; b[p*2  ][1] = r1;
                    b[p*2+1][0] = r2; b[p*2+1][1] = r3;
                } else {
                    int row = wn*32 + p*16 + lr;
                    int off = row*128 + k16*32 + lc*16;
                    ldsm4(r0, r1, r2, r3, bsB[s] + SWZ(off));
                    b[p*2  ][0] = r0; b[p*2  ][1] = r2;
                    b[p*2+1][0] = r1; b[p*2+1][1] = r3;
                }
            }
            #pragma unroll
            for (int mt = 0; mt < 2; mt++)
                #pragma unroll
                for (int nt = 0; nt < 4; nt++)
                    mma16816(acc[mt][nt], a[mt], b[nt]);
        }
        __syncthreads();
    }

    int g = lane >> 2, t4 = lane & 3;
    #pragma unroll
    for (int mt = 0; mt < 2; mt++)
        #pragma unroll
        for (int nt = 0; nt < 4; nt++){
            int r = m0 + wm*32 + mt*16 + g;
            int c = n0 + wn*32 + nt*8 + t4*2;
            epi(kb, r,     c, acc[mt][nt][0], acc[mt][nt][1]);
            epi(kb, r + 8, c, acc[mt][nt][2], acc[mt][nt][3]);
        }
}

// ---------------- fused LSTM GEMM + pointwise ----------------
// gate-permuted layout: one warp n-tile (32 cols) = 1 group of 8 units x 4 gates;
// nt = gate index, so each thread holds i/f/g/o for its (row, unit) in registers.
// FIRST: A = gnn, B = Wp_ih; epilogue stores xtp16 and does step-1 (c_old = 0).
// else:  A = h,   B = Wp_hh; epilogue adds xtp16 and does one step.
template<bool FIRST>
__global__ void __launch_bounds__(256, 2) gemm_lstm()
{
    __shared__ bf16 As[2][128*64];
    __shared__ bf16 Bs[2][64*64];

    int n0 = blockIdx.x*64, m0 = blockIdx.y*128, kb = blockIdx.z;

    const bf16* A = (FIRST ? g_bgnn : g_bh) + (size_t)kb*NN*HD;
    const bf16* B = (FIRST ? g_bwihp : g_bwhhp) + (size_t)kb*G4*HD;

    int tid = threadIdx.x, lane = tid & 31, wid = tid >> 5;
    int wm = wid & 3, wn = wid >> 2;
    uint32_t asB[2], bsB[2];
    asB[0] = (uint32_t)__cvta_generic_to_shared(&As[0][0]);
    asB[1] = (uint32_t)__cvta_generic_to_shared(&As[1][0]);
    bsB[0] = (uint32_t)__cvta_generic_to_shared(&Bs[0][0]);
    bsB[1] = (uint32_t)__cvta_generic_to_shared(&Bs[1][0]);

    float acc[2][4][4];
    #pragma unroll
    for (int a = 0; a < 2; a++)
        #pragma unroll
        for (int b = 0; b < 4; b++)
            #pragma unroll
            for (int e = 0; e < 4; e++) acc[a][b][e] = 0.f;

    auto load_tile = [&](int kt, int s){
        #pragma unroll
        for (int i = 0; i < 4; i++){
            int idx = tid + i*256;
            int row = idx >> 3, c = idx & 7;
            int off = row*128 + c*16;
            cpasync16(asB[s] + SWZ(off), A + (size_t)(m0+row)*HD + kt*64 + c*8);
        }
        #pragma unroll
        for (int i = 0; i < 2; i++){
            int idx = tid + i*256;
            int row = idx >> 3, c = idx & 7;
            int off = row*128 + c*16;
            cpasync16(bsB[s] + SWZ(off), B + (size_t)(n0 + row)*HD + kt*64 + c*8);
        }
        asm volatile("cp.async.commit_group;\n" ::: "memory");
    };

    load_tile(0, 0);
    int lr = lane & 15, lc = lane >> 4;
    #pragma unroll 1
    for (int kt = 0; kt < 4; kt++){
        if (kt + 1 < 4){
            load_tile(kt+1, (kt+1)&1);
            asm volatile("cp.async.wait_group 1;\n" ::: "memory");
        } else {
            asm volatile("cp.async.wait_group 0;\n" ::: "memory");
        }
        __syncthreads();
        int s = kt & 1;
        #pragma unroll
        for (int k16 = 0; k16 < 4; k16++){
            uint32_t a[2][4];
            #pragma unroll
            for (int mt = 0; mt < 2; mt++){
                int row = wm*32 + mt*16 + lr;
                int off = row*128 + k16*32 + lc*16;
                ldsm4(a[mt][0], a[mt][1], a[mt][2], a[mt][3], asB[s] + SWZ(off));
            }
            uint32_t b[4][2];
            #pragma unroll
            for (int p = 0; p < 2; p++){
                uint32_t r0, r1, r2, r3;
                int row = wn*32 + p*16 + lr;
                int off = row*128 + k16*32 + lc*16;
                ldsm4(r0, r1, r2, r3, bsB[s] + SWZ(off));
                b[p*2  ][0] = r0; b[p*2  ][1] = r2;
                b[p*2+1][0] = r1; b[p*2+1][1] = r3;
            }
            #pragma unroll
            for (int mt = 0; mt < 2; mt++)
                #pragma unroll
                for (int nt = 0; nt < 4; nt++)
                    mma16816(acc[mt][nt], a[mt], b[nt]);
        }
        __syncthreads();
    }

    // ---- fused epilogue: gates -> (c, h) ----
    int g = lane >> 2, t4 = lane & 3;
    int group = (n0 + wn*32) >> 5;
    int ubase = group*8 + t4*2;                 // unit pair (ubase, ubase+1)
    #pragma unroll
    for (int mt = 0; mt < 2; mt++){
        #pragma unroll
        for (int rh = 0; rh < 2; rh++){
            int rr = m0 + wm*32 + mt*16 + g + rh*8;
            size_t xrow = ((size_t)kb*NN + rr)*G4 + n0 + wn*32 + t4*2;
            float gv[4][2];                     // [gate][unit01]
            #pragma unroll
            for (int nt = 0; nt < 4; nt++){
                float v0 = acc[mt][nt][rh*2+0];
                float v1 = acc[mt][nt][rh*2+1];
                if (FIRST){
                    const float2 bb = *reinterpret_cast<const float2*>(
                        &g_bcomb[kb*G4 + n0 + wn*32 + nt*8 + t4*2]);
                    v0 += bb.x; v1 += bb.y;
                    *reinterpret_cast<bf162*>(&g_xtp16[xrow + nt*8]) =
                        __floats2bfloat162_rn(v0, v1);
                } else {
                    bf162 xp = *reinterpret_cast<const bf162*>(&g_xtp16[xrow + nt*8]);
                    v0 += __bfloat162float(xp.x);
                    v1 += __bfloat162float(xp.y);
                }
                gv[nt][0] = v0; gv[nt][1] = v1;
            }
            size_t ci = ((size_t)kb*NN + rr)*HD + ubase;
            float c0_old = 0.f, c1_old = 0.f;
            if (!FIRST){
                float2 co = *reinterpret_cast<const float2*>(&g_c[ci]);
                c0_old = co.x; c1_old = co.y;
            }
            float cn0 = sigf(gv[1][0])*c0_old + sigf(gv[0][0])*tanhf_(gv[2][0]);
            float cn1 = sigf(gv[1][1])*c1_old + sigf(gv[0][1])*tanhf_(gv[2][1]);
            float hn0 = sigf(gv[3][0])*tanhf_(cn0);
            float hn1 = sigf(gv[3][1])*tanhf_(cn1);
            *reinterpret_cast<float2*>(&g_c[ci]) = make_float2(cn0, cn1);
            *reinterpret_cast<bf162*>(&g_bh[ci]) = __floats2bfloat162_rn(hn0, hn1);
        }
    }
}

// ---------------- final: pred + res_z_bar ----------------
__global__ void __launch_bounds__(256) final_out(const float* __restrict__ x,
                                                 float* __restrict__ out)
{
    int idx = blockIdx.x*256 + threadIdx.x;   // over NN*FD
    int f = idx & 255;
    bool sl = (f >= 10) && (f < FD - 3);      // START=10, F_DIM-END=253
    float xv = x[idx];
    float d0 = g_delta[idx];
    float d1 = g_delta[(size_t)NN*FD + idx];
    float d2 = g_delta[(size_t)2*NN*FD + idx];
    float z0 = xv + d0, z1 = xv + d1, z2 = xv + d2;
    if (sl){ z0 = sigf(z0); z1 = sigf(z1); z2 = sigf(z2); }
    size_t zb = (size_t)NN*FD + (size_t)idx*3;
    out[zb + 0] = z0; out[zb + 1] = z1; out[zb + 2] = z2;
    float dm = (d0 + d1 + d2) * (1.f/3.f);
    float p = xv + dm;
    if (sl) p = sigf(p);
    out[idx] = p;
}

// ---------------- launch ----------------
extern "C" void kernel_launch(void* const* d_in, const int* in_sizes, int n_in,
                              void* d_out, int out_size)
{
    const float* x     = (const float*)d_in[0];
    const float* gnn_w = (const float*)d_in[1];
    const float* gnn_b = (const float*)d_in[2];
    const float* w_ih  = (const float*)d_in[3];
    const float* w_hh  = (const float*)d_in[4];
    const float* b_ih  = (const float*)d_in[5];
    const float* b_hh  = (const float*)d_in[6];
    const float* fc_w  = (const float*)d_in[7];
    const float* fc_b  = (const float*)d_in[8];
    const int*   adj   = (const int*)d_in[9];
    float* out = (float*)d_out;

    (void)in_sizes; (void)n_in; (void)out_size;

    prep_bf16<<<512, 256>>>(x, gnn_w, w_ih, w_hh, b_ih, b_hh, fc_w);
    adj_pass<<<NN, 256>>>(adj, out + (size_t)NN*FD*(1 + KG));

    // s16 = bf16(dinv * (x @ gnn_w[k]))
    gemm_bf<256, 256, true,  false, EpiXW><<<dim3(4, 32, 3), 256>>>(0, 0, EpiXW{});
    // gnn_out[k] = dinv_i * ((Abin[k]+I) @ s[k]) + b     (grid n,k,m for L2 A reuse)
    gemm_bf<4096, 256, true, true,  EpiGCN><<<dim3(4, 3, 32), 256>>>(3, 1, EpiGCN{gnn_b});
    // xtp = gnn @ Wp_ih^T + b (stored bf16, permuted) fused with LSTM step 1
    gemm_lstm<true><<<dim3(16, 32, 3), 256>>>();
    // steps 2..5: gates = h @ Wp_hh^T + xtp, fused pointwise
    for (int t = 1; t < TST; t++)
        gemm_lstm<false><<<dim3(16, 32, 3), 256>>>();
    // delta = tanh(h @ fc_w^T + fc_b)
    gemm_bf<256, 256, false, false, EpiFC><<<dim3(4, 32, 3), 256>>>(2, 2, EpiFC{fc_b});
    final_out<<<NN*FD/256, 256>>>(x, out);
}

// round 7
// speedup vs baseline: 3.2443x; 1.0815x over previous
#include <cuda_runtime.h>
#include <cuda_bf16.h>
#include <cstdint>
#include <cstddef>

#define NN 4096
#define FD 256
#define HD 256
#define KG 3
#define G4 1024
#define TST 5

typedef __nv_bfloat16 bf16;
typedef __nv_bfloat162 bf162;

// ---------------- scratch (device globals) ----------------
static __device__ __align__(16) bf16 g_bx[NN*FD];
static __device__ __align__(16) bf16 g_bgw[KG*FD*HD];
static __device__ __align__(16) uint8_t g_wihp8[KG*G4*HD];          // fp8(16*w), gate-permuted
static __device__ __align__(16) uint8_t g_whhp8[KG*G4*HD];          // fp8(16*w), gate-permuted
static __device__ __align__(16) uint8_t g_fcw8[KG*FD*HD];           // fp8(16*w)
static __device__ __align__(16) uint8_t g_a8[(size_t)KG*NN*NN];     // fp8 adjacency planes (+I), exact
static __device__ __align__(16) uint8_t g_sT8[(size_t)KG*HD*NN];    // fp8(64*dinv_j*xw), TRANSPOSED [h][j]
static __device__ __align__(16) uint8_t g_gnn8[(size_t)KG*NN*HD];   // fp8 gnn out
static __device__ __align__(16) uint8_t g_h8[(size_t)KG*NN*HD];     // fp8 lstm h
static __device__ __align__(16) bf16 g_xtp16[(size_t)KG*NN*G4];     // x-part of gates, permuted, bf16

static __device__ float g_dinv[KG*NN];
static __device__ float g_bcomb[KG*G4];                              // b_ih + b_hh, permuted
static __device__ float g_c[(size_t)KG*NN*HD];
static __device__ float g_delta[(size_t)KG*NN*FD];

// ---------------- helpers ----------------
__device__ __forceinline__ float sigf(float x){
    x = fminf(fmaxf(x, -30.f), 30.f);
    return __fdividef(1.f, 1.f + __expf(-x));
}
__device__ __forceinline__ float tanhf_(float x){
    x = fminf(fmaxf(x, -15.f), 15.f);
    float e = __expf(2.f*x);
    return __fdividef(e - 1.f, e + 1.f);
}
__device__ __forceinline__ uint16_t f2e4m3x2(float lo, float hi){
    uint16_t r; asm("cvt.rn.satfinite.e4m3x2.f32 %0, %1, %2;" : "=h"(r) : "f"(hi), "f"(lo));
    return r;   // byte0 = lo, byte1 = hi
}
__device__ __forceinline__ uint8_t f2e4m3(float v){
    uint16_t r; asm("cvt.rn.satfinite.e4m3x2.f32 %0, %1, %2;" : "=h"(r) : "f"(0.f), "f"(v));
    return (uint8_t)r;
}
__device__ __forceinline__ void mma_f8(float* c, const uint32_t* a, const uint32_t* b){
    asm volatile(
        "mma.sync.aligned.m16n8k32.row.col.f32.e4m3.e4m3.f32 "
        "{%0,%1,%2,%3}, {%4,%5,%6,%7}, {%8,%9}, {%0,%1,%2,%3};"
        : "+f"(c[0]), "+f"(c[1]), "+f"(c[2]), "+f"(c[3])
        : "r"(a[0]), "r"(a[1]), "r"(a[2]), "r"(a[3]), "r"(b[0]), "r"(b[1]));
}
__device__ __forceinline__ void mma16816(float* c, const uint32_t* a, const uint32_t* b){
    asm volatile(
        "mma.sync.aligned.m16n8k16.row.col.f32.bf16.bf16.f32 "
        "{%0,%1,%2,%3}, {%4,%5,%6,%7}, {%8,%9}, {%0,%1,%2,%3};"
        : "+f"(c[0]), "+f"(c[1]), "+f"(c[2]), "+f"(c[3])
        : "r"(a[0]), "r"(a[1]), "r"(a[2]), "r"(a[3]), "r"(b[0]), "r"(b[1]));
}
__device__ __forceinline__ void ldsm4(uint32_t& r0, uint32_t& r1, uint32_t& r2, uint32_t& r3, uint32_t a){
    asm volatile("ldmatrix.sync.aligned.m8n8.x4.shared.b16 {%0,%1,%2,%3}, [%4];"
        : "=r"(r0), "=r"(r1), "=r"(r2), "=r"(r3) : "r"(a));
}
__device__ __forceinline__ void ldsm4t(uint32_t& r0, uint32_t& r1, uint32_t& r2, uint32_t& r3, uint32_t a){
    asm volatile("ldmatrix.sync.aligned.m8n8.x4.trans.shared.b16 {%0,%1,%2,%3}, [%4];"
        : "=r"(r0), "=r"(r1), "=r"(r2), "=r"(r3) : "r"(a));
}
__device__ __forceinline__ void cpasync16(uint32_t dst, const void* src){
    asm volatile("cp.async.cg.shared.global [%0], [%1], 16;\n" :: "r"(dst), "l"(src));
}
#define SWZ(off) ((off) ^ (((off) >> 3) & 0x70))

// ---------------- prep: conversions + gate permutation ----------------
// permuted gate index: cp = (u>>3)*32 + gate*8 + (u&7)
__global__ void __launch_bounds__(256) prep_conv(
    const float* __restrict__ x, const float* __restrict__ gw,
    const float* __restrict__ wih, const float* __restrict__ whh,
    const float* __restrict__ bih, const float* __restrict__ bhh,
    const float* __restrict__ fcw)
{
    int i = blockIdx.x*blockDim.x + threadIdx.x;
    int stride = gridDim.x*blockDim.x;
    for (int t = i; t < NN*FD; t += stride)    g_bx[t]   = __float2bfloat16_rn(x[t]);
    for (int t = i; t < KG*FD*HD; t += stride) g_bgw[t]  = __float2bfloat16_rn(gw[t]);
    for (int t = i; t < KG*FD*HD; t += stride) g_fcw8[t] = f2e4m3(16.f*fcw[t]);
    for (int t = i; t < KG*G4*HD; t += stride){
        int k = t / (G4*HD);
        int rem = t - k*(G4*HD);
        int cp = rem >> 8, h = rem & 255;
        int gate = (cp >> 3) & 3;
        int u = ((cp >> 5) << 3) | (cp & 7);
        int orig = k*G4*HD + (gate*256 + u)*HD + h;
        g_wihp8[t] = f2e4m3(16.f*wih[orig]);
        g_whhp8[t] = f2e4m3(16.f*whh[orig]);
    }
    for (int t = i; t < KG*G4; t += stride){
        int k = t >> 10, cp = t & 1023;
        int gate = (cp >> 3) & 3;
        int u = ((cp >> 5) << 3) | (cp & 7);
        g_bcomb[t] = bih[k*G4 + gate*256 + u] + bhh[k*G4 + gate*256 + u];
    }
}

// ---------------- adj pass: passthrough + fp8 planes (+I) + dinv ----------------
__global__ void __launch_bounds__(256) adj_pass(const int* __restrict__ adj,
                                                float* __restrict__ out_adj)
{
    int row = blockIdx.x;
    const int4* src = reinterpret_cast<const int4*>(adj + (size_t)row*NN*KG);
    float4* dst = reinterpret_cast<float4*>(out_adj + (size_t)row*NN*KG);
    int c0 = 0, c1 = 0, c2 = 0;
    #pragma unroll
    for (int it = 0; it < 4; it++){
        int jg = threadIdx.x + it*256;               // group of 4 j's
        int4 v0 = src[jg*3+0];
        int4 v1 = src[jg*3+1];
        int4 v2 = src[jg*3+2];
        dst[jg*3+0] = make_float4((float)v0.x,(float)v0.y,(float)v0.z,(float)v0.w);
        dst[jg*3+1] = make_float4((float)v1.x,(float)v1.y,(float)v1.z,(float)v1.w);
        dst[jg*3+2] = make_float4((float)v2.x,(float)v2.y,(float)v2.z,(float)v2.w);
        // e4m3: 1.0f = 0x38
        uint32_t q0 = (v0.x?0x38u:0u) | ((v0.w?0x38u:0u)<<8) | ((v1.z?0x38u:0u)<<16) | ((v2.y?0x38u:0u)<<24);
        uint32_t q1 = (v0.y?0x38u:0u) | ((v1.x?0x38u:0u)<<8) | ((v1.w?0x38u:0u)<<16) | ((v2.z?0x38u:0u)<<24);
        uint32_t q2 = (v0.z?0x38u:0u) | ((v1.y?0x38u:0u)<<8) | ((v2.x?0x38u:0u)<<16) | ((v2.w?0x38u:0u)<<24);
        size_t base = (size_t)row*NN + jg*4;
        *reinterpret_cast<uint32_t*>(&g_a8[base])                   = q0;
        *reinterpret_cast<uint32_t*>(&g_a8[(size_t)NN*NN + base])   = q1;
        *reinterpret_cast<uint32_t*>(&g_a8[(size_t)2*NN*NN + base]) = q2;
        c0 += (v0.x?1:0) + (v0.w?1:0) + (v1.z?1:0) + (v2.y?1:0);
        c1 += (v0.y?1:0) + (v1.x?1:0) + (v1.w?1:0) + (v2.z?1:0);
        c2 += (v0.z?1:0) + (v1.y?1:0) + (v2.x?1:0) + (v2.w?1:0);
    }
    __shared__ int sm[3];
    if (threadIdx.x < 3) sm[threadIdx.x] = 0;
    __syncthreads();
    c0 = __reduce_add_sync(0xffffffffu, c0);
    c1 = __reduce_add_sync(0xffffffffu, c1);
    c2 = __reduce_add_sync(0xffffffffu, c2);
    if ((threadIdx.x & 31) == 0){
        atomicAdd(&sm[0], c0); atomicAdd(&sm[1], c1); atomicAdd(&sm[2], c2);
    }
    __syncthreads();
    if (threadIdx.x < 3){
        // self-loop: 0->1.0(0x38), 1->2.0(0x40); exact in e4m3
        size_t d = (size_t)threadIdx.x*NN*NN + (size_t)row*NN + row;
        g_a8[d] = (g_a8[d] == 0x38) ? 0x40 : 0x38;
        float deg = (float)(sm[threadIdx.x] + 1);
        g_dinv[threadIdx.x*NN + row] = rsqrtf(deg);
    }
}

// ---------------- XW GEMM (bf16): s = dinv*x@gnn_w, stored TRANSPOSED as fp8(64*s) ----------------
__global__ void __launch_bounds__(256, 2) gemm_xw()
{
    __shared__ bf16 As[2][128*64];
    __shared__ bf16 Bs[2][64*64];
    int n0 = blockIdx.x*64, m0 = blockIdx.y*128, kb = blockIdx.z;
    const bf16* A = g_bx;
    const bf16* B = g_bgw + (size_t)kb*FD*HD;

    int tid = threadIdx.x, lane = tid & 31, wid = tid >> 5;
    int wm = wid & 3, wn = wid >> 2;
    uint32_t asB[2], bsB[2];
    asB[0] = (uint32_t)__cvta_generic_to_shared(&As[0][0]);
    asB[1] = (uint32_t)__cvta_generic_to_shared(&As[1][0]);
    bsB[0] = (uint32_t)__cvta_generic_to_shared(&Bs[0][0]);
    bsB[1] = (uint32_t)__cvta_generic_to_shared(&Bs[1][0]);

    float acc[2][4][4];
    #pragma unroll
    for (int a = 0; a < 2; a++)
        #pragma unroll
        for (int b = 0; b < 4; b++)
            #pragma unroll
            for (int e = 0; e < 4; e++) acc[a][b][e] = 0.f;

    auto load_tile = [&](int kt, int s){
        #pragma unroll
        for (int i = 0; i < 4; i++){
            int idx = tid + i*256;
            int row = idx >> 3, c = idx & 7;
            cpasync16(asB[s] + SWZ(row*128 + c*16), A + (size_t)(m0+row)*HD + kt*64 + c*8);
        }
        #pragma unroll
        for (int i = 0; i < 2; i++){
            int idx = tid + i*256;
            int row = idx >> 3, c = idx & 7;
            cpasync16(bsB[s] + SWZ(row*128 + c*16), B + (size_t)(kt*64 + row)*HD + n0 + c*8);
        }
        asm volatile("cp.async.commit_group;\n" ::: "memory");
    };

    load_tile(0, 0);
    int lr = lane & 15, lc = lane >> 4;
    for (int kt = 0; kt < 4; kt++){
        if (kt + 1 < 4){
            load_tile(kt+1, (kt+1)&1);
            asm volatile("cp.async.wait_group 1;\n" ::: "memory");
        } else {
            asm volatile("cp.async.wait_group 0;\n" ::: "memory");
        }
        __syncthreads();
        int s = kt & 1;
        #pragma unroll
        for (int k16 = 0; k16 < 4; k16++){
            uint32_t a[2][4];
            #pragma unroll
            for (int mt = 0; mt < 2; mt++){
                int row = wm*32 + mt*16 + lr;
                ldsm4(a[mt][0], a[mt][1], a[mt][2], a[mt][3], asB[s] + SWZ(row*128 + k16*32 + lc*16));
            }
            uint32_t b[4][2];
            #pragma unroll
            for (int p = 0; p < 2; p++){
                uint32_t r0, r1, r2, r3;
                int row = k16*16 + lr;
                ldsm4t(r0, r1, r2, r3, bsB[s] + SWZ(row*128 + (wn*32 + p*16 + lc*8)*2));
                b[p*2  ][0] = r0; b[p*2  ][1] = r1;
                b[p*2+1][0] = r2; b[p*2+1][1] = r3;
            }
            #pragma unroll
            for (int mt = 0; mt < 2; mt++)
                #pragma unroll
                for (int nt = 0; nt < 4; nt++)
                    mma16816(acc[mt][nt], a[mt], b[nt]);
        }
        __syncthreads();
    }

    int g = lane >> 2, t4 = lane & 3;
    #pragma unroll
    for (int mt = 0; mt < 2; mt++)
        #pragma unroll
        for (int nt = 0; nt < 4; nt++)
            #pragma unroll
            for (int rh = 0; rh < 2; rh++){
                int r = m0 + wm*32 + mt*16 + g + rh*8;
                int c = n0 + wn*32 + nt*8 + t4*2;
                float sc = 64.f * g_dinv[kb*NN + r];
                size_t tb = (size_t)kb*HD*NN;
                g_sT8[tb + (size_t)c*NN + r]     = f2e4m3(sc*acc[mt][nt][rh*2+0]);
                g_sT8[tb + (size_t)(c+1)*NN + r] = f2e4m3(sc*acc[mt][nt][rh*2+1]);
            }
}

// ---------------- fp8 epilogues ----------------
struct EpiGCN {
    const float* gb;
    __device__ void operator()(int k, int r, int c, float v0, float v1) const {
        float di = g_dinv[k*NN + r] * (1.f/64.f);
        size_t i = ((size_t)k*NN + r)*HD + c;
        *reinterpret_cast<uint16_t*>(&g_gnn8[i]) =
            f2e4m3x2(di*v0 + gb[k*HD + c], di*v1 + gb[k*HD + c + 1]);
    }
};
struct EpiFC {
    const float* fcb;
    __device__ void operator()(int k, int r, int c, float v0, float v1) const {
        size_t i = ((size_t)k*NN + r)*FD + c;
        g_delta[i]   = tanhf_(v0*(1.f/16.f) + fcb[k*FD + c]);
        g_delta[i+1] = tanhf_(v1*(1.f/16.f) + fcb[k*FD + c + 1]);
    }
};

// ---------------- fp8 GEMM: BM=128, BN=64, BK=128 bytes, double-buffered ----------------
// A row-major [M][KD] fp8; B n-major [NC][KD] fp8 (row = output col, bytes = k).
template<int KD, int NC, bool GORD, class Epi>
__global__ void __launch_bounds__(256, 2) gemm_f8(int a_sel, int b_sel, Epi epi)
{
    __shared__ uint8_t As[2][128*128];
    __shared__ uint8_t Bs[2][64*128];

    int n0, m0, kb;
    if (GORD){ n0 = blockIdx.x*64; kb = blockIdx.y; m0 = blockIdx.z*128; }
    else     { n0 = blockIdx.x*64; m0 = blockIdx.y*128; kb = blockIdx.z; }

    const uint8_t* A = (a_sel == 0) ? g_a8 + (size_t)kb*NN*NN
                                    : g_h8 + (size_t)kb*NN*HD;
    const uint8_t* B = (b_sel == 0) ? g_sT8 + (size_t)kb*HD*NN
                                    : g_fcw8 + (size_t)kb*FD*HD;

    int tid = threadIdx.x, lane = tid & 31, wid = tid >> 5;
    int wm = wid & 3, wn = wid >> 2;
    uint32_t asB[2], bsB[2];
    asB[0] = (uint32_t)__cvta_generic_to_shared(&As[0][0]);
    asB[1] = (uint32_t)__cvta_generic_to_shared(&As[1][0]);
    bsB[0] = (uint32_t)__cvta_generic_to_shared(&Bs[0][0]);
    bsB[1] = (uint32_t)__cvta_generic_to_shared(&Bs[1][0]);

    float acc[2][4][4];
    #pragma unroll
    for (int a = 0; a < 2; a++)
        #pragma unroll
        for (int b = 0; b < 4; b++)
            #pragma unroll
            for (int e = 0; e < 4; e++) acc[a][b][e] = 0.f;

    constexpr int KT = KD/128;

    auto load_tile = [&](int kt, int s){
        #pragma unroll
        for (int i = 0; i < 4; i++){
            int idx = tid + i*256;
            int row = idx >> 3, c = idx & 7;
            cpasync16(asB[s] + SWZ(row*128 + c*16), A + (size_t)(m0+row)*KD + kt*128 + c*16);
        }
        #pragma unroll
        for (int i = 0; i < 2; i++){
            int idx = tid + i*256;
            int row = idx >> 3, c = idx & 7;
            cpasync16(bsB[s] + SWZ(row*128 + c*16), B + (size_t)(n0+row)*KD + kt*128 + c*16);
        }
        asm volatile("cp.async.commit_group;\n" ::: "memory");
    };

    load_tile(0, 0);
    int lr = lane & 15, lc = lane >> 4;
    for (int kt = 0; kt < KT; kt++){
        if (kt + 1 < KT){
            load_tile(kt+1, (kt+1)&1);
            asm volatile("cp.async.wait_group 1;\n" ::: "memory");
        } else {
            asm volatile("cp.async.wait_group 0;\n" ::: "memory");
        }
        __syncthreads();
        int s = kt & 1;
        #pragma unroll
        for (int c32 = 0; c32 < 4; c32++){
            uint32_t a[2][4];
            #pragma unroll
            for (int mt = 0; mt < 2; mt++){
                int row = wm*32 + mt*16 + lr;
                ldsm4(a[mt][0], a[mt][1], a[mt][2], a[mt][3], asB[s] + SWZ(row*128 + c32*32 + lc*16));
            }
            uint32_t b[4][2];
            #pragma unroll
            for (int p = 0; p < 2; p++){
                uint32_t r0, r1, r2, r3;
                int row = wn*32 + p*16 + lr;
                ldsm4(r0, r1, r2, r3, bsB[s] + SWZ(row*128 + c32*32 + lc*16));
                b[p*2  ][0] = r0; b[p*2  ][1] = r2;
                b[p*2+1][0] = r1; b[p*2+1][1] = r3;
            }
            #pragma unroll
            for (int mt = 0; mt < 2; mt++)
                #pragma unroll
                for (int nt = 0; nt < 4; nt++)
                    mma_f8(acc[mt][nt], a[mt], b[nt]);
        }
        __syncthreads();
    }

    int g = lane >> 2, t4 = lane & 3;
    #pragma unroll
    for (int mt = 0; mt < 2; mt++)
        #pragma unroll
        for (int nt = 0; nt < 4; nt++){
            int r = m0 + wm*32 + mt*16 + g;
            int c = n0 + wn*32 + nt*8 + t4*2;
            epi(kb, r,     c, acc[mt][nt][0], acc[mt][nt][1]);
            epi(kb, r + 8, c, acc[mt][nt][2], acc[mt][nt][3]);
        }
}

// ---------------- fused fp8 LSTM GEMM + pointwise ----------------
template<bool FIRST>
__global__ void __launch_bounds__(256, 2) gemm_lstm()
{
    __shared__ uint8_t As[2][128*128];
    __shared__ uint8_t Bs[2][64*128];

    int n0 = blockIdx.x*64, m0 = blockIdx.y*128, kb = blockIdx.z;

    const uint8_t* A = (FIRST ? g_gnn8 : g_h8) + (size_t)kb*NN*HD;
    const uint8_t* B = (FIRST ? g_wihp8 : g_whhp8) + (size_t)kb*G4*HD;

    int tid = threadIdx.x, lane = tid & 31, wid = tid >> 5;
    int wm = wid & 3, wn = wid >> 2;
    uint32_t asB[2], bsB[2];
    asB[0] = (uint32_t)__cvta_generic_to_shared(&As[0][0]);
    asB[1] = (uint32_t)__cvta_generic_to_shared(&As[1][0]);
    bsB[0] = (uint32_t)__cvta_generic_to_shared(&Bs[0][0]);
    bsB[1] = (uint32_t)__cvta_generic_to_shared(&Bs[1][0]);

    float acc[2][4][4];
    #pragma unroll
    for (int a = 0; a < 2; a++)
        #pragma unroll
        for (int b = 0; b < 4; b++)
            #pragma unroll
            for (int e = 0; e < 4; e++) acc[a][b][e] = 0.f;

    auto load_tile = [&](int kt, int s){
        #pragma unroll
        for (int i = 0; i < 4; i++){
            int idx = tid + i*256;
            int row = idx >> 3, c = idx & 7;
            cpasync16(asB[s] + SWZ(row*128 + c*16), A + (size_t)(m0+row)*HD + kt*128 + c*16);
        }
        #pragma unroll
        for (int i = 0; i < 2; i++){
            int idx = tid + i*256;
            int row = idx >> 3, c = idx & 7;
            cpasync16(bsB[s] + SWZ(row*128 + c*16), B + (size_t)(n0+row)*HD + kt*128 + c*16);
        }
        asm volatile("cp.async.commit_group;\n" ::: "memory");
    };

    load_tile(0, 0);
    int lr = lane & 15, lc = lane >> 4;
    #pragma unroll
    for (int kt = 0; kt < 2; kt++){
        if (kt == 0){
            load_tile(1, 1);
            asm volatile("cp.async.wait_group 1;\n" ::: "memory");
        } else {
            asm volatile("cp.async.wait_group 0;\n" ::: "memory");
        }
        __syncthreads();
        int s = kt & 1;
        #pragma unroll
        for (int c32 = 0; c32 < 4; c32++){
            uint32_t a[2][4];
            #pragma unroll
            for (int mt = 0; mt < 2; mt++){
                int row = wm*32 + mt*16 + lr;
                ldsm4(a[mt][0], a[mt][1], a[mt][2], a[mt][3], asB[s] + SWZ(row*128 + c32*32 + lc*16));
            }
            uint32_t b[4][2];
            #pragma unroll
            for (int p = 0; p < 2; p++){
                uint32_t r0, r1, r2, r3;
                int row = wn*32 + p*16 + lr;
                ldsm4(r0, r1, r2, r3, bsB[s] + SWZ(row*128 + c32*32 + lc*16));
                b[p*2  ][0] = r0; b[p*2  ][1] = r2;
                b[p*2+1][0] = r1; b[p*2+1][1] = r3;
            }
            #pragma unroll
            for (int mt = 0; mt < 2; mt++)
                #pragma unroll
                for (int nt = 0; nt < 4; nt++)
                    mma_f8(acc[mt][nt], a[mt], b[nt]);
        }
        __syncthreads();
    }

    // ---- fused epilogue: gates -> (c, h) ----
    int g = lane >> 2, t4 = lane & 3;
    int group = (n0 + wn*32) >> 5;
    int ubase = group*8 + t4*2;                 // unit pair (ubase, ubase+1)
    #pragma unroll
    for (int mt = 0; mt < 2; mt++){
        #pragma unroll
        for (int rh = 0; rh < 2; rh++){
            int rr = m0 + wm*32 + mt*16 + g + rh*8;
            size_t xrow = ((size_t)kb*NN + rr)*G4 + n0 + wn*32 + t4*2;
            float gv[4][2];                     // [gate][unit01]
            #pragma unroll
            for (int nt = 0; nt < 4; nt++){
                float v0 = acc[mt][nt][rh*2+0] * (1.f/16.f);
                float v1 = acc[mt][nt][rh*2+1] * (1.f/16.f);
                if (FIRST){
                    const float2 bb = *reinterpret_cast<const float2*>(
                        &g_bcomb[kb*G4 + n0 + wn*32 + nt*8 + t4*2]);
                    v0 += bb.x; v1 += bb.y;
                    *reinterpret_cast<bf162*>(&g_xtp16[xrow + nt*8]) =
                        __floats2bfloat162_rn(v0, v1);
                } else {
                    bf162 xp = *reinterpret_cast<const bf162*>(&g_xtp16[xrow + nt*8]);
                    v0 += __bfloat162float(xp.x);
                    v1 += __bfloat162float(xp.y);
                }
                gv[nt][0] = v0; gv[nt][1] = v1;
            }
            size_t ci = ((size_t)kb*NN + rr)*HD + ubase;
            float c0_old = 0.f, c1_old = 0.f;
            if (!FIRST){
                float2 co = *reinterpret_cast<const float2*>(&g_c[ci]);
                c0_old = co.x; c1_old = co.y;
            }
            float cn0 = sigf(gv[1][0])*c0_old + sigf(gv[0][0])*tanhf_(gv[2][0]);
            float cn1 = sigf(gv[1][1])*c1_old + sigf(gv[0][1])*tanhf_(gv[2][1]);
            float hn0 = sigf(gv[3][0])*tanhf_(cn0);
            float hn1 = sigf(gv[3][1])*tanhf_(cn1);
            *reinterpret_cast<float2*>(&g_c[ci]) = make_float2(cn0, cn1);
            *reinterpret_cast<uint16_t*>(&g_h8[ci]) = f2e4m3x2(hn0, hn1);
        }
    }
}

// ---------------- final: pred + res_z_bar ----------------
__global__ void __launch_bounds__(256) final_out(const float* __restrict__ x,
                                                 float* __restrict__ out)
{
    int idx = blockIdx.x*256 + threadIdx.x;   // over NN*FD
    int f = idx & 255;
    bool sl = (f >= 10) && (f < FD - 3);      // START=10, F_DIM-END=253
    float xv = x[idx];
    float d0 = g_delta[idx];
    float d1 = g_delta[(size_t)NN*FD + idx];
    float d2 = g_delta[(size_t)2*NN*FD + idx];
    float z0 = xv + d0, z1 = xv + d1, z2 = xv + d2;
    if (sl){ z0 = sigf(z0); z1 = sigf(z1); z2 = sigf(z2); }
    size_t zb = (size_t)NN*FD + (size_t)idx*3;
    out[zb + 0] = z0; out[zb + 1] = z1; out[zb + 2] = z2;
    float dm = (d0 + d1 + d2) * (1.f/3.f);
    float p = xv + dm;
    if (sl) p = sigf(p);
    out[idx] = p;
}

// ---------------- launch ----------------
extern "C" void kernel_launch(void* const* d_in, const int* in_sizes, int n_in,
                              void* d_out, int out_size)
{
    const float* x     = (const float*)d_in[0];
    const float* gnn_w = (const float*)d_in[1];
    const float* gnn_b = (const float*)d_in[2];
    const float* w_ih  = (const float*)d_in[3];
    const float* w_hh  = (const float*)d_in[4];
    const float* b_ih  = (const float*)d_in[5];
    const float* b_hh  = (const float*)d_in[6];
    const float* fc_w  = (const float*)d_in[7];
    const float* fc_b  = (const float*)d_in[8];
    const int*   adj   = (const int*)d_in[9];
    float* out = (float*)d_out;

    (void)in_sizes; (void)n_in; (void)out_size;

    prep_conv<<<512, 256>>>(x, gnn_w, w_ih, w_hh, b_ih, b_hh, fc_w);
    adj_pass<<<NN, 256>>>(adj, out + (size_t)NN*FD*(1 + KG));

    // sT8[h][j] = fp8(64 * dinv_j * (x @ gnn_w)[j][h])   (bf16 GEMM)
    gemm_xw<<<dim3(4, 32, 3), 256>>>();
    // gnn_out[k] = dinv_i * ((A+I) @ s)/64 + b           (fp8 GEMM, grid n,k,m for L2 A reuse)
    gemm_f8<4096, 256, true, EpiGCN><<<dim3(4, 3, 32), 256>>>(0, 0, EpiGCN{gnn_b});
    // xtp = gnn @ (16 Wp_ih)^T /16 + b, fused LSTM step 1
    gemm_lstm<true><<<dim3(16, 32, 3), 256>>>();
    // steps 2..5: gates = h @ (16 Wp_hh)^T /16 + xtp, fused pointwise
    for (int t = 1; t < TST; t++)
        gemm_lstm<false><<<dim3(16, 32, 3), 256>>>();
    // delta = tanh(h @ (16 fc_w)^T /16 + fc_b)
    gemm_f8<256, 256, false, EpiFC><<<dim3(4, 32, 3), 256>>>(1, 1, EpiFC{fc_b});
    final_out<<<NN*FD/256, 256>>>(x, out);
}